// round 15
// baseline (speedup 1.0000x reference)
#include <cuda_runtime.h>
#include <cuda_fp16.h>
#include <cstdint>

#define NMAX 50048
#define H 128
#define CAP 128                 // bucket capacity; P(Poisson(16) > 128) ~ 1e-80
#define NBUCKET 16

__device__ int   g_is64;
__device__ int   g_cnt[NMAX];
__device__ int   g_bucket[(size_t)NMAX * CAP];
__device__ float g_dinv[NMAX];
__device__ __align__(16) __half g_hhh[(size_t)NMAX * H];  // fp16 xW (unscaled)
__device__ __align__(16) float  g_y[(size_t)NMAX * H];
__device__ float g_stats2[2][NBUCKET][256];
__device__ float g_bnS[H];
__device__ float g_bnH[H];

// ---------------------------------------------------------------------------
// zero counters/stats + fused dtype probe (block 0)
__global__ void zero_kernel(const int* __restrict__ ei32, int e, int n) {
    int i = blockIdx.x * blockDim.x + threadIdx.x;
    if (i < n) g_cnt[i] = 0;
    if (i < 2 * NBUCKET * 256) ((float*)g_stats2)[i] = 0.0f;
    if (blockIdx.x == 0) {
        __shared__ int nz;
        if (threadIdx.x == 0) nz = 0;
        __syncthreads();
        int pos = 2 * threadIdx.x + 1;
        if (pos < 2 * e && ei32[pos] != 0) atomicAdd(&nz, 1);
        __syncthreads();
        if (threadIdx.x == 0) g_is64 = (nz == 0) ? 1 : 0;
    }
}

__device__ __forceinline__ int load_idx_(const void* eiv, size_t pos, int n,
                                         int is64) {
    int v;
    if (is64) v = (int)((const long long*)eiv)[pos];
    else      v = ((const int*)eiv)[pos];
    return min(max(v, 0), n - 1);
}

// direct bucket fill: 4 edges per thread for MLP on the atomic chain
__global__ void fill_kernel(const void* __restrict__ eiv, int e, int n) {
    int i = (blockIdx.x * blockDim.x + threadIdx.x) * 4;
    int is64 = g_is64;
    #pragma unroll
    for (int u = 0; u < 4; u++) {
        int idx = i + u;
        if (idx < e) {
            int s = load_idx_(eiv, (size_t)idx, n, is64);
            int d = load_idx_(eiv, (size_t)e + idx, n, is64);
            int slot = atomicAdd(&g_cnt[d], 1);
            if (slot < CAP) g_bucket[(size_t)d * CAP + slot] = s;
        }
    }
}

__global__ void dinv_kernel(int n) {
    int i = blockIdx.x * blockDim.x + threadIdx.x;
    if (i < n) g_dinv[i] = rsqrtf((float)min(g_cnt[i], CAP) + 1.0f);
}

// ---------------------------------------------------------------------------
// GEMM: g_hhh[row] = fp16( f(X[row]) @ W )   (dinv applied in agg)
//   mode 0: X = Xext, f = identity
//   mode 1: X = g_y, f = relu(bn affine); BN params from g_stats2[0] prologue
#define KC 32
__global__ void __launch_bounds__(256)
gemm_kernel(const float* __restrict__ Xext, const float* __restrict__ W,
            int n, int mode,
            const float* __restrict__ gamma, const float* __restrict__ beta) {
    __shared__ float Xs[128][KC + 1];
    __shared__ float Ws[KC][128];
    __shared__ float bnS[H], bnH[H];

    const float* X = (mode == 1) ? (const float*)g_y : Xext;

    int tid = threadIdx.x;
    int row0 = blockIdx.x * 128;
    int tx = tid & 7;
    int ty = tid >> 3;

    if (mode == 1 && tid < 128) {
        float s = 0.f, q = 0.f;
        #pragma unroll
        for (int b = 0; b < NBUCKET; b++) {
            s += g_stats2[0][b][tid];
            q += g_stats2[0][b][128 + tid];
        }
        float inv_n = 1.0f / (float)n;
        float mu = s * inv_n;
        float var = q * inv_n - mu * mu;
        float istd = rsqrtf(var + 1e-5f);
        float sc = gamma[tid] * istd;
        bnS[tid] = sc;
        bnH[tid] = beta[tid] - mu * sc;
    }

    int xr[4], xc[4], wr[4], wc[4];
    #pragma unroll
    for (int u = 0; u < 4; u++) {
        int i = tid + u * 256;
        xr[u] = i >> 3;  xc[u] = i & 7;
        wr[u] = i >> 5;  wc[u] = i & 31;
    }

    float4 xv[4], wv[4];
    #pragma unroll
    for (int u = 0; u < 4; u++) {
        int grow = row0 + xr[u];
        xv[u] = (grow < n) ? *(const float4*)(X + (size_t)grow * H + xc[u] * 4)
                           : make_float4(0.f, 0.f, 0.f, 0.f);
        wv[u] = *(const float4*)(W + (size_t)wr[u] * H + wc[u] * 4);
    }

    unsigned long long acc[4][8];
    #pragma unroll
    for (int r = 0; r < 4; r++)
        #pragma unroll
        for (int j = 0; j < 8; j++) acc[r][j] = 0ull;

    #pragma unroll
    for (int cch = 0; cch < 4; cch++) {
        int kc = cch * KC;
        __syncthreads();
        #pragma unroll
        for (int u = 0; u < 4; u++) {
            float4 v = xv[u];
            if (mode == 1) {
                int c = kc + xc[u] * 4;
                v.x = fmaxf(fmaf(v.x, bnS[c + 0], bnH[c + 0]), 0.f);
                v.y = fmaxf(fmaf(v.y, bnS[c + 1], bnH[c + 1]), 0.f);
                v.z = fmaxf(fmaf(v.z, bnS[c + 2], bnH[c + 2]), 0.f);
                v.w = fmaxf(fmaf(v.w, bnS[c + 3], bnH[c + 3]), 0.f);
            }
            Xs[xr[u]][xc[u] * 4 + 0] = v.x;
            Xs[xr[u]][xc[u] * 4 + 1] = v.y;
            Xs[xr[u]][xc[u] * 4 + 2] = v.z;
            Xs[xr[u]][xc[u] * 4 + 3] = v.w;
            *(float4*)&Ws[wr[u]][wc[u] * 4] = wv[u];
        }
        __syncthreads();

        if (cch < 3) {
            int kn = kc + KC;
            #pragma unroll
            for (int u = 0; u < 4; u++) {
                int grow = row0 + xr[u];
                xv[u] = (grow < n)
                    ? *(const float4*)(X + (size_t)grow * H + kn + xc[u] * 4)
                    : make_float4(0.f, 0.f, 0.f, 0.f);
                wv[u] = *(const float4*)(W + (size_t)(kn + wr[u]) * H + wc[u] * 4);
            }
        }

        #pragma unroll
        for (int k = 0; k < KC; k++) {
            unsigned long long a[4];
            #pragma unroll
            for (int r = 0; r < 4; r++) {
                unsigned int ai = __float_as_uint(Xs[ty * 4 + r][k]);
                asm("mov.b64 %0, {%1, %1};" : "=l"(a[r]) : "r"(ai));
            }
            const unsigned long long* bp = (const unsigned long long*)&Ws[k][0];
            unsigned long long b[8];
            #pragma unroll
            for (int j = 0; j < 8; j++) b[j] = bp[j * 8 + tx];
            #pragma unroll
            for (int r = 0; r < 4; r++)
                #pragma unroll
                for (int j = 0; j < 8; j++)
                    asm("fma.rn.f32x2 %0, %1, %2, %0;"
                        : "+l"(acc[r][j]) : "l"(a[r]), "l"(b[j]));
        }
    }

    #pragma unroll
    for (int r = 0; r < 4; r++) {
        int row = row0 + ty * 4 + r;
        if (row < n) {
            __half* o = g_hhh + (size_t)row * H + tx * 2;
            #pragma unroll
            for (int j = 0; j < 8; j++) {
                unsigned int lo, hi;
                asm("mov.b64 {%0, %1}, %2;" : "=r"(lo), "=r"(hi) : "l"(acc[r][j]));
                __half2 h = __floats2half2_rn(__uint_as_float(lo),
                                              __uint_as_float(hi));
                *(__half2*)(o + j * 16) = h;
            }
        }
    }
}

// ---------------------------------------------------------------------------
// aggregation + fused BN stats: one warp per node, uint4 half-warp gather —
// one warp load covers TWO neighbor rows (16 lanes x 16B = 256B = one row).
__device__ __forceinline__ void accum8(float* a, uint4 v, float f) {
    float2 p0 = __half22float2(*(const __half2*)&v.x);
    float2 p1 = __half22float2(*(const __half2*)&v.y);
    float2 p2 = __half22float2(*(const __half2*)&v.z);
    float2 p3 = __half22float2(*(const __half2*)&v.w);
    a[0] = fmaf(p0.x, f, a[0]); a[1] = fmaf(p0.y, f, a[1]);
    a[2] = fmaf(p1.x, f, a[2]); a[3] = fmaf(p1.y, f, a[3]);
    a[4] = fmaf(p2.x, f, a[4]); a[5] = fmaf(p2.y, f, a[5]);
    a[6] = fmaf(p3.x, f, a[6]); a[7] = fmaf(p3.y, f, a[7]);
}

__global__ void __launch_bounds__(256)
agg_kernel(const float* __restrict__ bias, int n, int slot) {
    __shared__ float red[8][128];
    __shared__ float redq[8][128];

    int w = threadIdx.x >> 5;
    int lane = threadIdx.x & 31;
    int half = lane >> 4;     // 0 or 1
    int hl = lane & 15;       // lane within half; owns cols hl*8..hl*8+7
    int d = blockIdx.x * 8 + w;
    bool active = d < n;

    float outv[8];
    #pragma unroll
    for (int k = 0; k < 8; k++) outv[k] = 0.f;

    if (active) {
        const uint4* hh4 = (const uint4*)g_hhh;   // 16 uint4 per row
        int cnt_total = min(g_cnt[d], CAP);
        float dvd = g_dinv[d];

        float acc[8];
        #pragma unroll
        for (int k = 0; k < 8; k++) acc[k] = 0.f;

        // self-loop: half 0 contributes, half 1 scaled by 0
        {
            uint4 v = hh4[d * 16 + hl];
            accum8(acc, v, (half == 0) ? dvd : 0.f);
        }

        const int* row = g_bucket + d * CAP;
        for (int j0 = 0; j0 < cnt_total; j0 += 32) {
            bool ok = (j0 + lane < cnt_total);
            int idx = ok ? row[j0 + lane] : 0;
            float dvv = ok ? g_dinv[idx] : 0.f;
            int cnt = min(32, cnt_total - j0);
            int t = 0;
            // 8 neighbors per iteration (4 uint4 loads in flight)
            for (; t + 7 < cnt; t += 8) {
                int s0 = __shfl_sync(0xffffffffu, idx, t + 0 + half);
                int s1 = __shfl_sync(0xffffffffu, idx, t + 2 + half);
                int s2 = __shfl_sync(0xffffffffu, idx, t + 4 + half);
                int s3 = __shfl_sync(0xffffffffu, idx, t + 6 + half);
                float f0 = __shfl_sync(0xffffffffu, dvv, t + 0 + half);
                float f1 = __shfl_sync(0xffffffffu, dvv, t + 2 + half);
                float f2 = __shfl_sync(0xffffffffu, dvv, t + 4 + half);
                float f3 = __shfl_sync(0xffffffffu, dvv, t + 6 + half);
                uint4 v0 = hh4[s0 * 16 + hl];
                uint4 v1 = hh4[s1 * 16 + hl];
                uint4 v2 = hh4[s2 * 16 + hl];
                uint4 v3 = hh4[s3 * 16 + hl];
                accum8(acc, v0, f0);
                accum8(acc, v1, f1);
                accum8(acc, v2, f2);
                accum8(acc, v3, f3);
            }
            // tail: 2 neighbors per iteration; src==cnt (odd tail) has dvv=0
            for (; t < cnt; t += 2) {
                int s = __shfl_sync(0xffffffffu, idx, t + half);
                float f = __shfl_sync(0xffffffffu, dvv, t + half);
                uint4 v = hh4[s * 16 + hl];
                accum8(acc, v, f);
            }
        }

        // merge halves: lane i += lane i+16
        #pragma unroll
        for (int k = 0; k < 8; k++)
            acc[k] += __shfl_down_sync(0xffffffffu, acc[k], 16);

        if (half == 0) {
            const float4* b4 = (const float4*)bias;
            float4 bb0 = b4[hl * 2];
            float4 bb1 = b4[hl * 2 + 1];
            outv[0] = fmaf(acc[0], dvd, bb0.x);
            outv[1] = fmaf(acc[1], dvd, bb0.y);
            outv[2] = fmaf(acc[2], dvd, bb0.z);
            outv[3] = fmaf(acc[3], dvd, bb0.w);
            outv[4] = fmaf(acc[4], dvd, bb1.x);
            outv[5] = fmaf(acc[5], dvd, bb1.y);
            outv[6] = fmaf(acc[6], dvd, bb1.z);
            outv[7] = fmaf(acc[7], dvd, bb1.w);
            float4* gy4 = (float4*)g_y;
            gy4[d * 32 + hl * 2] =
                make_float4(outv[0], outv[1], outv[2], outv[3]);
            gy4[d * 32 + hl * 2 + 1] =
                make_float4(outv[4], outv[5], outv[6], outv[7]);
        }
    }

    if (half == 0) {
        #pragma unroll
        for (int k = 0; k < 8; k++) {
            red[w][hl * 8 + k] = outv[k];
            redq[w][hl * 8 + k] = outv[k] * outv[k];
        }
    }
    __syncthreads();

    int tid = threadIdx.x;
    if (tid < 128) {
        float s = 0.f, q = 0.f;
        #pragma unroll
        for (int i = 0; i < 8; i++) { s += red[i][tid]; q += redq[i][tid]; }
        float* bucket = &g_stats2[slot][blockIdx.x & (NBUCKET - 1)][0];
        atomicAdd(&bucket[tid], s);
        atomicAdd(&bucket[128 + tid], q);
    }
}

// ---------------------------------------------------------------------------
// parallel bucket reduce -> BN params (layer 2 only; layer 1 folded into gemm2)
__global__ void bnreduce_kernel(const float* __restrict__ g,
                                const float* __restrict__ beta,
                                int n, int slot) {
    __shared__ float ss[128], qq[128];
    int t = threadIdx.x;
    int c = t & 127;
    int half = t >> 7;
    float s = 0.f, q = 0.f;
    #pragma unroll
    for (int b = half * (NBUCKET / 2); b < (half + 1) * (NBUCKET / 2); b++) {
        s += g_stats2[slot][b][c];
        q += g_stats2[slot][b][128 + c];
    }
    if (half == 1) { ss[c] = s; qq[c] = q; }
    __syncthreads();
    if (half == 0) {
        s += ss[c]; q += qq[c];
        float inv_n = 1.0f / (float)n;
        float mu = s * inv_n;
        float var = q * inv_n - mu * mu;
        float istd = rsqrtf(var + 1e-5f);
        float sc = g[c] * istd;
        g_bnS[c] = sc;
        g_bnH[c] = beta[c] - mu * sc;
    }
}

__global__ void out_kernel(float* __restrict__ out, int n) {
    int i = blockIdx.x * blockDim.x + threadIdx.x;
    if (i >= n * 32) return;
    int c = (i & 31) * 4;
    float4 v = ((const float4*)g_y)[i];
    v.x = fmaxf(fmaf(v.x, g_bnS[c + 0], g_bnH[c + 0]), 0.f);
    v.y = fmaxf(fmaf(v.y, g_bnS[c + 1], g_bnH[c + 1]), 0.f);
    v.z = fmaxf(fmaf(v.z, g_bnS[c + 2], g_bnH[c + 2]), 0.f);
    v.w = fmaxf(fmaf(v.w, g_bnS[c + 3], g_bnH[c + 3]), 0.f);
    ((float4*)out)[i] = v;
}

// ---------------------------------------------------------------------------
extern "C" void kernel_launch(void* const* d_in, const int* in_sizes, int n_in,
                              void* d_out, int out_size) {
    const float* node_feat = (const float*)d_in[0];
    const void*  ei        = d_in[1];
    const float* W1   = (const float*)d_in[2];
    const float* b1   = (const float*)d_in[3];
    const float* W2   = (const float*)d_in[4];
    const float* b2   = (const float*)d_in[5];
    const float* g1   = (const float*)d_in[6];
    const float* beta1= (const float*)d_in[7];
    const float* g2   = (const float*)d_in[8];
    const float* beta2= (const float*)d_in[9];

    int n = in_sizes[0] / H;
    int e = in_sizes[1] / 2;

    int nb256 = (n + 255) / 256;
    int fill_blocks = ((e + 3) / 4 + 255) / 256;
    int gemm_blocks = (n + 127) / 128;
    int agg_blocks = (n + 7) / 8;

    // fork: gemm1 has no graph dependency -> side stream, concurrent with prep
    cudaStream_t s2;
    cudaEvent_t evFork, evJoin;
    cudaStreamCreateWithFlags(&s2, cudaStreamNonBlocking);
    cudaEventCreateWithFlags(&evFork, cudaEventDisableTiming);
    cudaEventCreateWithFlags(&evJoin, cudaEventDisableTiming);

    cudaEventRecord(evFork, 0);
    cudaStreamWaitEvent(s2, evFork, 0);
    gemm_kernel<<<gemm_blocks, 256, 0, s2>>>(node_feat, W1, n, 0,
                                             nullptr, nullptr);
    cudaEventRecord(evJoin, s2);

    zero_kernel<<<nb256, 256>>>((const int*)ei, e, n);
    fill_kernel<<<fill_blocks, 256>>>(ei, e, n);
    dinv_kernel<<<nb256, 256>>>(n);

    cudaStreamWaitEvent(0, evJoin, 0);   // join before agg1

    agg_kernel<<<agg_blocks, 256>>>(b1, n, 0);
    gemm_kernel<<<gemm_blocks, 256>>>(nullptr, W2, n, 1, g1, beta1);
    agg_kernel<<<agg_blocks, 256>>>(b2, n, 1);
    bnreduce_kernel<<<1, 256>>>(g2, beta2, n, 1);

    out_kernel<<<(n * 32 + 255) / 256, 256>>>((float*)d_out, n);
}

// round 16
// speedup vs baseline: 1.1183x; 1.1183x over previous
#include <cuda_runtime.h>
#include <cuda_fp16.h>
#include <cstdint>

#define NMAX 50048
#define H 128
#define CAP 128                 // bucket capacity; P(Poisson(16) > 128) ~ 1e-80
#define NBUCKET 16

__device__ int   g_is64;
__device__ int   g_cnt[NMAX];
__device__ int   g_bucket[(size_t)NMAX * CAP];
__device__ float g_dinv[NMAX];
__device__ __align__(16) __half g_hhh[(size_t)NMAX * H];  // fp16 xW (unscaled)
__device__ __align__(16) float  g_y[(size_t)NMAX * H];
__device__ float g_stats2[2][NBUCKET][256];

// ---------------------------------------------------------------------------
// zero counters/stats + fused dtype probe (block 0)
__global__ void zero_kernel(const int* __restrict__ ei32, int e, int n) {
    int i = blockIdx.x * blockDim.x + threadIdx.x;
    if (i < n) g_cnt[i] = 0;
    if (i < 2 * NBUCKET * 256) ((float*)g_stats2)[i] = 0.0f;
    if (blockIdx.x == 0) {
        __shared__ int nz;
        if (threadIdx.x == 0) nz = 0;
        __syncthreads();
        int pos = 2 * threadIdx.x + 1;
        if (pos < 2 * e && ei32[pos] != 0) atomicAdd(&nz, 1);
        __syncthreads();
        if (threadIdx.x == 0) g_is64 = (nz == 0) ? 1 : 0;
    }
}

__device__ __forceinline__ int load_idx_(const void* eiv, size_t pos, int n,
                                         int is64) {
    int v;
    if (is64) v = (int)((const long long*)eiv)[pos];
    else      v = ((const int*)eiv)[pos];
    return min(max(v, 0), n - 1);
}

// direct bucket fill: 4 edges per thread for MLP on the atomic chain
__global__ void fill_kernel(const void* __restrict__ eiv, int e, int n) {
    int i = (blockIdx.x * blockDim.x + threadIdx.x) * 4;
    int is64 = g_is64;
    #pragma unroll
    for (int u = 0; u < 4; u++) {
        int idx = i + u;
        if (idx < e) {
            int s = load_idx_(eiv, (size_t)idx, n, is64);
            int d = load_idx_(eiv, (size_t)e + idx, n, is64);
            int slot = atomicAdd(&g_cnt[d], 1);
            if (slot < CAP) g_bucket[(size_t)d * CAP + slot] = s;
        }
    }
}

__global__ void dinv_kernel(int n) {
    int i = blockIdx.x * blockDim.x + threadIdx.x;
    if (i < n) g_dinv[i] = rsqrtf((float)min(g_cnt[i], CAP) + 1.0f);
}

// ---------------------------------------------------------------------------
// compute BN affine params from stat buckets into smem (per-block redundant)
__device__ __forceinline__ void bn_params_from_stats(
    int slot, int n, const float* __restrict__ gamma,
    const float* __restrict__ beta, float* bnS, float* bnH, int tid) {
    if (tid < 128) {
        float s = 0.f, q = 0.f;
        #pragma unroll
        for (int b = 0; b < NBUCKET; b++) {
            s += g_stats2[slot][b][tid];
            q += g_stats2[slot][b][128 + tid];
        }
        float inv_n = 1.0f / (float)n;
        float mu = s * inv_n;
        float var = q * inv_n - mu * mu;
        float istd = rsqrtf(var + 1e-5f);
        float sc = gamma[tid] * istd;
        bnS[tid] = sc;
        bnH[tid] = beta[tid] - mu * sc;
    }
}

// ---------------------------------------------------------------------------
// GEMM: g_hhh[row] = fp16( f(X[row]) @ W )   (dinv applied in agg)
//   mode 0: X = Xext, f = identity
//   mode 1: X = g_y, f = relu(bn affine); BN params from g_stats2[0] prologue
#define KC 32
__global__ void __launch_bounds__(256)
gemm_kernel(const float* __restrict__ Xext, const float* __restrict__ W,
            int n, int mode,
            const float* __restrict__ gamma, const float* __restrict__ beta) {
    __shared__ float Xs[128][KC + 1];
    __shared__ float Ws[KC][128];
    __shared__ float bnS[H], bnH[H];

    const float* X = (mode == 1) ? (const float*)g_y : Xext;

    int tid = threadIdx.x;
    int row0 = blockIdx.x * 128;
    int tx = tid & 7;
    int ty = tid >> 3;

    if (mode == 1)
        bn_params_from_stats(0, n, gamma, beta, bnS, bnH, tid);

    int xr[4], xc[4], wr[4], wc[4];
    #pragma unroll
    for (int u = 0; u < 4; u++) {
        int i = tid + u * 256;
        xr[u] = i >> 3;  xc[u] = i & 7;
        wr[u] = i >> 5;  wc[u] = i & 31;
    }

    float4 xv[4], wv[4];
    #pragma unroll
    for (int u = 0; u < 4; u++) {
        int grow = row0 + xr[u];
        xv[u] = (grow < n) ? *(const float4*)(X + (size_t)grow * H + xc[u] * 4)
                           : make_float4(0.f, 0.f, 0.f, 0.f);
        wv[u] = *(const float4*)(W + (size_t)wr[u] * H + wc[u] * 4);
    }

    unsigned long long acc[4][8];
    #pragma unroll
    for (int r = 0; r < 4; r++)
        #pragma unroll
        for (int j = 0; j < 8; j++) acc[r][j] = 0ull;

    #pragma unroll
    for (int cch = 0; cch < 4; cch++) {
        int kc = cch * KC;
        __syncthreads();
        #pragma unroll
        for (int u = 0; u < 4; u++) {
            float4 v = xv[u];
            if (mode == 1) {
                int c = kc + xc[u] * 4;
                v.x = fmaxf(fmaf(v.x, bnS[c + 0], bnH[c + 0]), 0.f);
                v.y = fmaxf(fmaf(v.y, bnS[c + 1], bnH[c + 1]), 0.f);
                v.z = fmaxf(fmaf(v.z, bnS[c + 2], bnH[c + 2]), 0.f);
                v.w = fmaxf(fmaf(v.w, bnS[c + 3], bnH[c + 3]), 0.f);
            }
            Xs[xr[u]][xc[u] * 4 + 0] = v.x;
            Xs[xr[u]][xc[u] * 4 + 1] = v.y;
            Xs[xr[u]][xc[u] * 4 + 2] = v.z;
            Xs[xr[u]][xc[u] * 4 + 3] = v.w;
            *(float4*)&Ws[wr[u]][wc[u] * 4] = wv[u];
        }
        __syncthreads();

        if (cch < 3) {
            int kn = kc + KC;
            #pragma unroll
            for (int u = 0; u < 4; u++) {
                int grow = row0 + xr[u];
                xv[u] = (grow < n)
                    ? *(const float4*)(X + (size_t)grow * H + kn + xc[u] * 4)
                    : make_float4(0.f, 0.f, 0.f, 0.f);
                wv[u] = *(const float4*)(W + (size_t)(kn + wr[u]) * H + wc[u] * 4);
            }
        }

        #pragma unroll
        for (int k = 0; k < KC; k++) {
            unsigned long long a[4];
            #pragma unroll
            for (int r = 0; r < 4; r++) {
                unsigned int ai = __float_as_uint(Xs[ty * 4 + r][k]);
                asm("mov.b64 %0, {%1, %1};" : "=l"(a[r]) : "r"(ai));
            }
            const unsigned long long* bp = (const unsigned long long*)&Ws[k][0];
            unsigned long long b[8];
            #pragma unroll
            for (int j = 0; j < 8; j++) b[j] = bp[j * 8 + tx];
            #pragma unroll
            for (int r = 0; r < 4; r++)
                #pragma unroll
                for (int j = 0; j < 8; j++)
                    asm("fma.rn.f32x2 %0, %1, %2, %0;"
                        : "+l"(acc[r][j]) : "l"(a[r]), "l"(b[j]));
        }
    }

    #pragma unroll
    for (int r = 0; r < 4; r++) {
        int row = row0 + ty * 4 + r;
        if (row < n) {
            __half* o = g_hhh + (size_t)row * H + tx * 2;
            #pragma unroll
            for (int j = 0; j < 8; j++) {
                unsigned int lo, hi;
                asm("mov.b64 {%0, %1}, %2;" : "=r"(lo), "=r"(hi) : "l"(acc[r][j]));
                __half2 h = __floats2half2_rn(__uint_as_float(lo),
                                              __uint_as_float(hi));
                *(__half2*)(o + j * 16) = h;
            }
        }
    }
}

// ---------------------------------------------------------------------------
// aggregation + fused BN stats: one warp per node, fp16 uint2 gather,
// per-neighbor dinv via shuffled scalar (R12-proven layout).
__device__ __forceinline__ void addh2s(float4& a, uint2 v, float s) {
    float2 p0 = __half22float2(*(const __half2*)&v.x);
    float2 p1 = __half22float2(*(const __half2*)&v.y);
    a.x = fmaf(p0.x, s, a.x); a.y = fmaf(p0.y, s, a.y);
    a.z = fmaf(p1.x, s, a.z); a.w = fmaf(p1.y, s, a.w);
}

__global__ void __launch_bounds__(256)
agg_kernel(const float* __restrict__ bias, int n, int slot) {
    __shared__ float red[8][128];
    __shared__ float redq[8][128];

    int w = threadIdx.x >> 5;
    int lane = threadIdx.x & 31;
    int d = blockIdx.x * 8 + w;
    bool active = d < n;

    float4 out = make_float4(0.f, 0.f, 0.f, 0.f);
    if (active) {
        const uint2* hh2 = (const uint2*)g_hhh;
        int cnt_total = min(g_cnt[d], CAP);
        float dvd = g_dinv[d];
        float4 acc = make_float4(0.f, 0.f, 0.f, 0.f);
        addh2s(acc, hh2[d * 32 + lane], dvd);   // self-loop

        const int* row = g_bucket + d * CAP;
        for (int j0 = 0; j0 < cnt_total; j0 += 32) {
            bool ok = (j0 + lane < cnt_total);
            int idx = ok ? row[j0 + lane] : 0;
            float dvv = ok ? g_dinv[idx] : 0.f;
            int cnt = min(32, cnt_total - j0);
            int t = 0;
            for (; t + 3 < cnt; t += 4) {
                int s0 = __shfl_sync(0xffffffffu, idx, t + 0);
                int s1 = __shfl_sync(0xffffffffu, idx, t + 1);
                int s2 = __shfl_sync(0xffffffffu, idx, t + 2);
                int s3 = __shfl_sync(0xffffffffu, idx, t + 3);
                float f0 = __shfl_sync(0xffffffffu, dvv, t + 0);
                float f1 = __shfl_sync(0xffffffffu, dvv, t + 1);
                float f2 = __shfl_sync(0xffffffffu, dvv, t + 2);
                float f3 = __shfl_sync(0xffffffffu, dvv, t + 3);
                uint2 v0 = hh2[s0 * 32 + lane];
                uint2 v1 = hh2[s1 * 32 + lane];
                uint2 v2 = hh2[s2 * 32 + lane];
                uint2 v3 = hh2[s3 * 32 + lane];
                addh2s(acc, v0, f0); addh2s(acc, v1, f1);
                addh2s(acc, v2, f2); addh2s(acc, v3, f3);
            }
            for (; t < cnt; t++) {
                int s = __shfl_sync(0xffffffffu, idx, t);
                float f = __shfl_sync(0xffffffffu, dvv, t);
                addh2s(acc, hh2[s * 32 + lane], f);
            }
        }

        float4 bb = *(const float4*)(bias + lane * 4);
        out.x = fmaf(acc.x, dvd, bb.x);
        out.y = fmaf(acc.y, dvd, bb.y);
        out.z = fmaf(acc.z, dvd, bb.z);
        out.w = fmaf(acc.w, dvd, bb.w);
        ((float4*)g_y)[d * 32 + lane] = out;
    }

    red[w][lane * 4 + 0] = out.x;  redq[w][lane * 4 + 0] = out.x * out.x;
    red[w][lane * 4 + 1] = out.y;  redq[w][lane * 4 + 1] = out.y * out.y;
    red[w][lane * 4 + 2] = out.z;  redq[w][lane * 4 + 2] = out.z * out.z;
    red[w][lane * 4 + 3] = out.w;  redq[w][lane * 4 + 3] = out.w * out.w;
    __syncthreads();

    int tid = threadIdx.x;
    if (tid < 128) {
        float s = 0.f, q = 0.f;
        #pragma unroll
        for (int i = 0; i < 8; i++) { s += red[i][tid]; q += redq[i][tid]; }
        float* bucket = &g_stats2[slot][blockIdx.x & (NBUCKET - 1)][0];
        atomicAdd(&bucket[tid], s);
        atomicAdd(&bucket[128 + tid], q);
    }
}

// ---------------------------------------------------------------------------
// final output: BN params computed in-block from g_stats2[1], then
// out = relu(bn(y)). 128 rows per block, 16 float4 per thread.
__global__ void __launch_bounds__(256)
out_kernel(float* __restrict__ out, int n,
           const float* __restrict__ gamma, const float* __restrict__ beta) {
    __shared__ float bnS[H], bnH[H];
    int tid = threadIdx.x;
    bn_params_from_stats(1, n, gamma, beta, bnS, bnH, tid);
    __syncthreads();

    int base = blockIdx.x * 4096;   // 128 rows * 32 float4
    int limit = n * 32;
    #pragma unroll
    for (int u = 0; u < 16; u++) {
        int i = base + u * 256 + tid;
        if (i < limit) {
            int c = (i & 31) * 4;
            float4 v = ((const float4*)g_y)[i];
            v.x = fmaxf(fmaf(v.x, bnS[c + 0], bnH[c + 0]), 0.f);
            v.y = fmaxf(fmaf(v.y, bnS[c + 1], bnH[c + 1]), 0.f);
            v.z = fmaxf(fmaf(v.z, bnS[c + 2], bnH[c + 2]), 0.f);
            v.w = fmaxf(fmaf(v.w, bnS[c + 3], bnH[c + 3]), 0.f);
            ((float4*)out)[i] = v;
        }
    }
}

// ---------------------------------------------------------------------------
extern "C" void kernel_launch(void* const* d_in, const int* in_sizes, int n_in,
                              void* d_out, int out_size) {
    const float* node_feat = (const float*)d_in[0];
    const void*  ei        = d_in[1];
    const float* W1   = (const float*)d_in[2];
    const float* b1   = (const float*)d_in[3];
    const float* W2   = (const float*)d_in[4];
    const float* b2   = (const float*)d_in[5];
    const float* g1   = (const float*)d_in[6];
    const float* beta1= (const float*)d_in[7];
    const float* g2   = (const float*)d_in[8];
    const float* beta2= (const float*)d_in[9];

    int n = in_sizes[0] / H;
    int e = in_sizes[1] / 2;

    int nb256 = (n + 255) / 256;
    int fill_blocks = ((e + 3) / 4 + 255) / 256;
    int gemm_blocks = (n + 127) / 128;
    int agg_blocks = (n + 7) / 8;

    // fork: gemm1 has no graph dependency -> side stream, concurrent with prep
    cudaStream_t s2;
    cudaEvent_t evFork, evJoin;
    cudaStreamCreateWithFlags(&s2, cudaStreamNonBlocking);
    cudaEventCreateWithFlags(&evFork, cudaEventDisableTiming);
    cudaEventCreateWithFlags(&evJoin, cudaEventDisableTiming);

    cudaEventRecord(evFork, 0);
    cudaStreamWaitEvent(s2, evFork, 0);
    gemm_kernel<<<gemm_blocks, 256, 0, s2>>>(node_feat, W1, n, 0,
                                             nullptr, nullptr);
    cudaEventRecord(evJoin, s2);

    zero_kernel<<<nb256, 256>>>((const int*)ei, e, n);
    fill_kernel<<<fill_blocks, 256>>>(ei, e, n);
    dinv_kernel<<<nb256, 256>>>(n);

    cudaStreamWaitEvent(0, evJoin, 0);   // join before agg1

    agg_kernel<<<agg_blocks, 256>>>(b1, n, 0);
    gemm_kernel<<<gemm_blocks, 256>>>(nullptr, W2, n, 1, g1, beta1);
    agg_kernel<<<agg_blocks, 256>>>(b2, n, 1);
    out_kernel<<<gemm_blocks, 256>>>((float*)d_out, n, g2, beta2);
}